// round 10
// baseline (speedup 1.0000x reference)
#include <cuda_runtime.h>
#include <cuda_bf16.h>

#define A_N   49104
#define B_N   8
#define C_N   80
#define M_N   64
#define TPB   256
#define XBLK  ((A_N + TPB - 1) / TPB)   /* 192 */
#define NBLK  (XBLK * B_N)              /* 1536 */
#define NWARP (TPB/32)

// Per-block partials (fully overwritten each launch before being read)
__device__ float    p_cls[NBLK];
__device__ float    p_reg[NBLK];
__device__ int      p_np[NBLK];
__device__ unsigned g_done = 0;         // reset by last block each launch

__device__ __forceinline__ float rcp_fast(float x) {
    float y; asm("rcp.approx.f32 %0, %1;" : "=f"(y) : "f"(x)); return y;
}
__device__ __forceinline__ float smooth_l1(float d) {
    return (d <= (1.0f/9.0f)) ? 4.5f * d * d : d - (0.5f/9.0f);
}
// Hot focal term, unclamped (inputs guaranteed in (1e-3, 1-1e-3)):
// p^2 * log2(1-p).  (x0.75 and x(-ln2) folded at the end)
__device__ __forceinline__ float bt(float p) {
    return p * p * __log2f(1.0f - p);
}
__device__ __forceinline__ float bt4(float4 v) {
    return (bt(v.x) + bt(v.y)) + (bt(v.z) + bt(v.w));
}
// Positive-class term, alpha folded: 0.25 * (1-p)^2 * log2(p)
__device__ __forceinline__ float pt(float p) {
    float q = 1.0f - p;
    return 0.25f * q * q * __log2f(p);
}

__global__ __launch_bounds__(TPB) void fl_main_kernel(
    const float* __restrict__ reg,    // [B, A, 4]
    const float* __restrict__ cls,    // [B, A, C]
    const float* __restrict__ anc,    // [1, A, 4]
    const float* __restrict__ gt,     // [B, M, 5]
    float* __restrict__ out)          // [2]
{
    __shared__ float4 s_gbox[M_N];
    __shared__ float  s_garea[M_N];
    __shared__ int    s_gcls[M_N];
    __shared__ float  s_flag[TPB];    // 0 = ignore/inactive, 0.75 = active
    __shared__ float  s_rc[NWARP];
    __shared__ float  s_rr[NWARP];
    __shared__ int    s_rn[NWARP];
    __shared__ float  s_bl[2 * B_N];
    __shared__ bool   s_last;

    const int b    = blockIdx.y;
    const int tid  = threadIdx.x;
    const int lane = tid & 31;

    if (tid < M_N) {
        const float* g = gt + ((size_t)b * M_N + tid) * 5;
        float x1 = g[0], y1 = g[1], x2 = g[2], y2 = g[3], c = g[4];
        if (c < 0.0f) { x1 = y1 = x2 = y2 = 0.0f; }  // invalid gt never wins argmax
        s_gbox[tid]  = make_float4(x1, y1, x2, y2);
        s_garea[tid] = (x2 - x1) * (y2 - y1);
        s_gcls[tid]  = (int)c;
    }
    __syncthreads();

    const int a       = blockIdx.x * TPB + tid;
    const float* clsb = cls + (size_t)b * A_N * C_N;

    float flag = 0.0f;   // 0 or 0.75
    float accS = 0.0f;   // pos-class correction (fully weighted, log2 units)
    float accR = 0.0f;   // smooth-L1 sum
    int   npos = 0;

    // ================= Phase 1: IoU argmax + assignment ====================
    if (a < A_N) {
        const float4 ab = *reinterpret_cast<const float4*>(anc + (size_t)a * 4);
        const float aw  = fabsf(ab.x - ab.z);
        const float ah  = fabsf(ab.y - ab.w);
        const float acx = ab.x + 0.5f * aw;
        const float acy = ab.y + 0.5f * ah;
        const float a_area = (ab.z - ab.x) * (ab.w - ab.y);

        // Packed-key argmax: key = (bits(2iw*2ih/S) & ~63) | m ; unsigned max.
        // r >= 0, so float ordering == unsigned ordering of the bits.
        unsigned key0 = 0u, key1 = 0u;
        #pragma unroll 8
        for (int m = 0; m < M_N; m += 2) {
            {
                const float4 gb = s_gbox[m];
                float iw = fminf(ab.z, gb.z) - fmaxf(ab.x, gb.x);
                float ih = fminf(ab.w, gb.w) - fmaxf(ab.y, gb.y);
                float u  = iw + fabsf(iw);          // 2*max(iw,0) (fma pipe)
                float v  = ih + fabsf(ih);
                float r  = (u * v) * rcp_fast(a_area + s_garea[m]);
                unsigned kk = (__float_as_uint(r) & 0xffffffc0u) | (unsigned)m;
                key0 = max(key0, kk);
            }
            {
                const float4 gb = s_gbox[m + 1];
                float iw = fminf(ab.z, gb.z) - fmaxf(ab.x, gb.x);
                float ih = fminf(ab.w, gb.w) - fmaxf(ab.y, gb.y);
                float u  = iw + fabsf(iw);
                float v  = ih + fabsf(ih);
                float r  = (u * v) * rcp_fast(a_area + s_garea[m + 1]);
                unsigned kk = (__float_as_uint(r) & 0xffffffc0u) | (unsigned)(m + 1);
                key1 = max(key1, kk);
            }
        }
        const int bidx = (int)(max(key0, key1) & 63u);

        // Exact IoU of the winner for thresholding
        const float4 gb = s_gbox[bidx];
        float iw = fmaxf(fminf(ab.z, gb.z) - fmaxf(ab.x, gb.x), 0.0f);
        float ih = fmaxf(fminf(ab.w, gb.w) - fmaxf(ab.y, gb.y), 0.0f);
        float inter = iw * ih;
        float un    = (a_area + s_garea[bidx]) - inter;
        float iou   = __fdividef(inter, un);
        const bool pos = (iou >= 0.5f);
        const bool neg = (iou < 0.4f);
        if (pos | neg) flag = 0.75f;

        if (pos) {
            float gw0 = gb.z - gb.x, gh0 = gb.w - gb.y;
            float gcx = gb.x + 0.5f * gw0, gcy = gb.y + 0.5f * gh0;
            float gw = fmaxf(gw0, 1.0f), gh = fmaxf(gh0, 1.0f);
            float tdx = __fdividef(gcx - acx, aw);
            float tdy = __fdividef(gcy - acy, ah);
            float tdh = __logf(__fdividef(gh, ah));
            float tdw = __logf(__fdividef(gw, aw));
            const float4 rg = *reinterpret_cast<const float4*>(reg + ((size_t)b * A_N + a) * 4);
            accR = smooth_l1(fabsf(tdx - rg.x)) + smooth_l1(fabsf(tdy - rg.y))
                 + smooth_l1(fabsf(tdh - rg.z)) + smooth_l1(fabsf(tdw - rg.w));
            npos = 1;
            // replace 0.75*base with the alpha-weighted positive term at (a,cid)
            const int cid = s_gcls[bidx];
            const float p = clsb[(size_t)a * C_N + cid];
            accS = pt(p) - 0.75f * bt(p);
        }
    }
    s_flag[tid] = flag;
    __syncwarp();

    // ====== Phase 2: flag-weighted focal stream (coalesced, branchless) ====
    const int sbase = tid & ~31;
    const int wbase = blockIdx.x * TPB + sbase;
    float accB0 = 0.0f, accB1 = 0.0f;

    if (wbase + 32 <= A_N) {
        const float4* wp = reinterpret_cast<const float4*>(clsb + (size_t)wbase * C_N);
        #pragma unroll
        for (int k = 0; k < 20; k += 2) {
            const int f0 = lane + 32 * k;
            const int f1 = f0 + 32;
            const float fl0 = s_flag[sbase + f0 / 20];
            const float fl1 = s_flag[sbase + f1 / 20];
            const float4 v0 = wp[f0];
            const float4 v1 = wp[f1];
            accB0 = fmaf(fl0, bt4(v0), accB0);
            accB1 = fmaf(fl1, bt4(v1), accB1);
        }
    } else {
        // Tail (last x-block only): guarded
        const float4* wp = reinterpret_cast<const float4*>(clsb + (size_t)wbase * C_N);
        for (int k = 0; k < 20; k++) {
            const int f  = lane + 32 * k;
            const int al = f / 20;
            if (wbase + al < A_N) {
                const float fl = s_flag[sbase + al];
                accB0 = fmaf(fl, bt4(wp[f]), accB0);
            }
        }
    }

    float accC = (accB0 + accB1) + accS;

    // ================= Block reduction -> per-block partials ===============
    #pragma unroll
    for (int o = 16; o > 0; o >>= 1) {
        accC += __shfl_down_sync(0xffffffffu, accC, o);
        accR += __shfl_down_sync(0xffffffffu, accR, o);
        npos += __shfl_down_sync(0xffffffffu, npos, o);
    }
    if (lane == 0) { s_rc[tid >> 5] = accC; s_rr[tid >> 5] = accR; s_rn[tid >> 5] = npos; }
    __syncthreads();

    const int blk = b * XBLK + blockIdx.x;
    if (tid == 0) {
        float c = 0.0f, r = 0.0f; int n = 0;
        #pragma unroll
        for (int w = 0; w < NWARP; w++) { c += s_rc[w]; r += s_rr[w]; n += s_rn[w]; }
        p_cls[blk] = c; p_reg[blk] = r; p_np[blk] = n;
        __threadfence();
        unsigned done = atomicAdd(&g_done, 1u);
        s_last = (done == NBLK - 1);
    }
    __syncthreads();

    // ================= Last block finalizes ================================
    if (s_last) {
        __threadfence();
        const int w = tid >> 5;
        if (w < B_N) {
            float c = 0.0f, r = 0.0f, n = 0.0f;
            for (int i = lane; i < XBLK; i += 32) {
                const int idx = w * XBLK + i;
                c += p_cls[idx]; r += p_reg[idx]; n += (float)p_np[idx];
            }
            #pragma unroll
            for (int o = 16; o > 0; o >>= 1) {
                c += __shfl_down_sync(0xffffffffu, c, o);
                r += __shfl_down_sync(0xffffffffu, r, o);
                n += __shfl_down_sync(0xffffffffu, n, o);
            }
            if (lane == 0) {
                const float NEG_LN2 = -0.69314718055994530942f;
                s_bl[w]       = NEG_LN2 * c / fmaxf(n, 1.0f);
                s_bl[B_N + w] = (n > 0.0f) ? r / (4.0f * n) : 0.0f;
            }
        }
        __syncthreads();
        if (tid == 0) {
            float cs = 0.0f, rs = 0.0f;
            #pragma unroll
            for (int i = 0; i < B_N; i++) { cs += s_bl[i]; rs += s_bl[B_N + i]; }
            out[0] = cs * (1.0f / (float)B_N);
            out[1] = rs * (1.0f / (float)B_N) * 50.0f;
            atomicExch(&g_done, 0u);   // reset for next graph replay
        }
    }
}

extern "C" void kernel_launch(void* const* d_in, const int* in_sizes, int n_in,
                              void* d_out, int out_size) {
    const float* regression     = (const float*)d_in[0];
    const float* classification = (const float*)d_in[1];
    const float* anchors        = (const float*)d_in[2];
    const float* gt_BB          = (const float*)d_in[3];
    float* out = (float*)d_out;

    dim3 grid(XBLK, B_N);
    fl_main_kernel<<<grid, TPB>>>(regression, classification, anchors, gt_BB, out);
}

// round 11
// speedup vs baseline: 1.0163x; 1.0163x over previous
#include <cuda_runtime.h>
#include <cuda_bf16.h>

#define A_N   49104
#define B_N   8
#define C_N   80
#define M_N   64
#define TPB   256
#define XBLK  ((A_N + TPB - 1) / TPB)   /* 192 */
#define NBLK  (XBLK * B_N)              /* 1536 */
#define NWARP (TPB/32)

// Per-block partials (fully overwritten each launch before being read)
__device__ float    p_cls[NBLK];
__device__ float    p_reg[NBLK];
__device__ int      p_np[NBLK];
__device__ unsigned g_done = 0;         // reset by last block each launch

__device__ __forceinline__ float rcp_fast(float x) {
    float y; asm("rcp.approx.f32 %0, %1;" : "=f"(y) : "f"(x)); return y;
}
__device__ __forceinline__ float smooth_l1(float d) {
    return (d <= (1.0f/9.0f)) ? 4.5f * d * d : d - (0.5f/9.0f);
}
// Hot focal quad: sum of p^2*log2(1-p), FFMA-chained (inputs in (1e-3,1-1e-3))
__device__ __forceinline__ float bt4s(float4 v) {
    float l0 = __log2f(1.0f - v.x);
    float l1 = __log2f(1.0f - v.y);
    float l2 = __log2f(1.0f - v.z);
    float l3 = __log2f(1.0f - v.w);
    float t  = (v.x * v.x) * l0;
    t = fmaf(v.y * v.y, l1, t);
    t = fmaf(v.z * v.z, l2, t);
    t = fmaf(v.w * v.w, l3, t);
    return t;
}
__device__ __forceinline__ float bt(float p) {
    return p * p * __log2f(1.0f - p);
}
// Positive-class term, alpha folded: 0.25 * (1-p)^2 * log2(p)
__device__ __forceinline__ float pt(float p) {
    float q = 1.0f - p;
    return 0.25f * q * q * __log2f(p);
}

__global__ __launch_bounds__(TPB) void fl_main_kernel(
    const float* __restrict__ reg,    // [B, A, 4]
    const float* __restrict__ cls,    // [B, A, C]
    const float* __restrict__ anc,    // [1, A, 4]
    const float* __restrict__ gt,     // [B, M, 5]
    float* __restrict__ out)          // [2]
{
    __shared__ float4 s_gbox[M_N];
    __shared__ float  s_garea[M_N];
    __shared__ int    s_gcls[M_N];
    __shared__ float  s_flag[TPB];    // 0 = ignore/inactive, 0.75 = active
    __shared__ float  s_rc[NWARP];
    __shared__ float  s_rr[NWARP];
    __shared__ int    s_rn[NWARP];
    __shared__ float  s_bl[2 * B_N];
    __shared__ bool   s_last;

    const int b    = blockIdx.y;
    const int tid  = threadIdx.x;
    const int lane = tid & 31;

    if (tid < M_N) {
        const float* g = gt + ((size_t)b * M_N + tid) * 5;
        float x1 = g[0], y1 = g[1], x2 = g[2], y2 = g[3], c = g[4];
        if (c < 0.0f) { x1 = y1 = x2 = y2 = 0.0f; }  // invalid gt never wins argmax
        s_gbox[tid]  = make_float4(x1, y1, x2, y2);
        s_garea[tid] = (x2 - x1) * (y2 - y1);
        s_gcls[tid]  = (int)c;
    }
    __syncthreads();

    const int a       = blockIdx.x * TPB + tid;
    const float* clsb = cls + (size_t)b * A_N * C_N;

    float flag = 0.0f;   // 0 or 0.75
    float accS = 0.0f;   // pos-class correction (fully weighted, log2 units)
    float accR = 0.0f;   // smooth-L1 sum
    int   npos = 0;

    // ================= Phase 1: IoU argmax + assignment ====================
    if (a < A_N) {
        const float4 ab = *reinterpret_cast<const float4*>(anc + (size_t)a * 4);
        const float aw  = fabsf(ab.x - ab.z);
        const float ah  = fabsf(ab.y - ab.w);
        const float acx = ab.x + 0.5f * aw;
        const float acy = ab.y + 0.5f * ah;
        const float a_area = (ab.z - ab.x) * (ab.w - ab.y);

        // Packed-key argmax, SIGNED int max:
        //   u = iw+|iw| >= 0 ;  r = u*ih*rcp(S)  (<=0 whenever no overlap)
        //   key = bits(r)|m ; negative r -> negative int -> loses to any r>=0.
        int key0 = (int)0x80000000, key1 = (int)0x80000000;
        #pragma unroll 8
        for (int m = 0; m < M_N; m += 2) {
            {
                const float4 gb = s_gbox[m];
                float iw = fminf(ab.z, gb.z) - fmaxf(ab.x, gb.x);
                float ih = fminf(ab.w, gb.w) - fmaxf(ab.y, gb.y);
                float u  = iw + fabsf(iw);
                float r  = (u * ih) * rcp_fast(a_area + s_garea[m]);
                int kk = (int)((__float_as_uint(r) & 0xffffffc0u) | (unsigned)m);
                key0 = (kk > key0) ? kk : key0;
            }
            {
                const float4 gb = s_gbox[m + 1];
                float iw = fminf(ab.z, gb.z) - fmaxf(ab.x, gb.x);
                float ih = fminf(ab.w, gb.w) - fmaxf(ab.y, gb.y);
                float u  = iw + fabsf(iw);
                float r  = (u * ih) * rcp_fast(a_area + s_garea[m + 1]);
                int kk = (int)((__float_as_uint(r) & 0xffffffc0u) | (unsigned)(m + 1));
                key1 = (kk > key1) ? kk : key1;
            }
        }
        const int kmax = (key0 > key1) ? key0 : key1;
        const int bidx = kmax & 63;

        // Exact IoU of the winner for thresholding
        const float4 gb = s_gbox[bidx];
        float iw = fmaxf(fminf(ab.z, gb.z) - fmaxf(ab.x, gb.x), 0.0f);
        float ih = fmaxf(fminf(ab.w, gb.w) - fmaxf(ab.y, gb.y), 0.0f);
        float inter = iw * ih;
        float un    = (a_area + s_garea[bidx]) - inter;
        float iou   = __fdividef(inter, un);
        const bool pos = (iou >= 0.5f);
        const bool neg = (iou < 0.4f);
        if (pos | neg) flag = 0.75f;

        if (pos) {
            float gw0 = gb.z - gb.x, gh0 = gb.w - gb.y;
            float gcx = gb.x + 0.5f * gw0, gcy = gb.y + 0.5f * gh0;
            float gw = fmaxf(gw0, 1.0f), gh = fmaxf(gh0, 1.0f);
            float tdx = __fdividef(gcx - acx, aw);
            float tdy = __fdividef(gcy - acy, ah);
            float tdh = __logf(__fdividef(gh, ah));
            float tdw = __logf(__fdividef(gw, aw));
            const float4 rg = *reinterpret_cast<const float4*>(reg + ((size_t)b * A_N + a) * 4);
            accR = smooth_l1(fabsf(tdx - rg.x)) + smooth_l1(fabsf(tdy - rg.y))
                 + smooth_l1(fabsf(tdh - rg.z)) + smooth_l1(fabsf(tdw - rg.w));
            npos = 1;
            // replace 0.75*base with the alpha-weighted positive term at (a,cid)
            const int cid = s_gcls[bidx];
            const float p = clsb[(size_t)a * C_N + cid];
            accS = pt(p) - 0.75f * bt(p);
        }
    }
    s_flag[tid] = flag;
    __syncwarp();

    // ====== Phase 2: flag-weighted focal stream (coalesced, branchless) ====
    const int sbase = tid & ~31;
    const int wbase = blockIdx.x * TPB + sbase;
    float accB0 = 0.0f, accB1 = 0.0f;

    if (wbase + 32 <= A_N) {
        // per-lane base pointer -> loads become immediate-offset LDGs
        const float4* tp = reinterpret_cast<const float4*>(
            clsb + (size_t)wbase * C_N) + lane;
        // flag index (lane+32k)/20 has period 5 in k: al(k)=alb[k%5]+8*(k/5)
        int alb[5];
        #pragma unroll
        for (int i = 0; i < 5; i++)
            alb[i] = (int)(((unsigned)lane + 32u * (unsigned)i) / 20u);

        #pragma unroll
        for (int k = 0; k < 20; k += 2) {
            const float fl0 = s_flag[sbase + alb[k % 5]       + 8 * (k / 5)];
            const float fl1 = s_flag[sbase + alb[(k + 1) % 5] + 8 * ((k + 1) / 5)];
            const float4 v0 = tp[32 * k];
            const float4 v1 = tp[32 * (k + 1)];
            accB0 = fmaf(fl0, bt4s(v0), accB0);
            accB1 = fmaf(fl1, bt4s(v1), accB1);
        }
    } else {
        // Tail (last x-block only): guarded
        const float4* wp = reinterpret_cast<const float4*>(clsb + (size_t)wbase * C_N);
        for (int k = 0; k < 20; k++) {
            const int f  = lane + 32 * k;
            const int al = f / 20;
            if (wbase + al < A_N) {
                const float fl = s_flag[sbase + al];
                accB0 = fmaf(fl, bt4s(wp[f]), accB0);
            }
        }
    }

    float accC = (accB0 + accB1) + accS;

    // ================= Block reduction -> per-block partials ===============
    #pragma unroll
    for (int o = 16; o > 0; o >>= 1) {
        accC += __shfl_down_sync(0xffffffffu, accC, o);
        accR += __shfl_down_sync(0xffffffffu, accR, o);
        npos += __shfl_down_sync(0xffffffffu, npos, o);
    }
    if (lane == 0) { s_rc[tid >> 5] = accC; s_rr[tid >> 5] = accR; s_rn[tid >> 5] = npos; }
    __syncthreads();

    const int blk = b * XBLK + blockIdx.x;
    if (tid == 0) {
        float c = 0.0f, r = 0.0f; int n = 0;
        #pragma unroll
        for (int w = 0; w < NWARP; w++) { c += s_rc[w]; r += s_rr[w]; n += s_rn[w]; }
        p_cls[blk] = c; p_reg[blk] = r; p_np[blk] = n;
        __threadfence();
        unsigned done = atomicAdd(&g_done, 1u);
        s_last = (done == NBLK - 1);
    }
    __syncthreads();

    // ================= Last block finalizes ================================
    if (s_last) {
        __threadfence();
        const int w = tid >> 5;
        if (w < B_N) {
            float c = 0.0f, r = 0.0f, n = 0.0f;
            for (int i = lane; i < XBLK; i += 32) {
                const int idx = w * XBLK + i;
                c += p_cls[idx]; r += p_reg[idx]; n += (float)p_np[idx];
            }
            #pragma unroll
            for (int o = 16; o > 0; o >>= 1) {
                c += __shfl_down_sync(0xffffffffu, c, o);
                r += __shfl_down_sync(0xffffffffu, r, o);
                n += __shfl_down_sync(0xffffffffu, n, o);
            }
            if (lane == 0) {
                const float NEG_LN2 = -0.69314718055994530942f;
                s_bl[w]       = NEG_LN2 * c / fmaxf(n, 1.0f);
                s_bl[B_N + w] = (n > 0.0f) ? r / (4.0f * n) : 0.0f;
            }
        }
        __syncthreads();
        if (tid == 0) {
            float cs = 0.0f, rs = 0.0f;
            #pragma unroll
            for (int i = 0; i < B_N; i++) { cs += s_bl[i]; rs += s_bl[B_N + i]; }
            out[0] = cs * (1.0f / (float)B_N);
            out[1] = rs * (1.0f / (float)B_N) * 50.0f;
            atomicExch(&g_done, 0u);   // reset for next graph replay
        }
    }
}

extern "C" void kernel_launch(void* const* d_in, const int* in_sizes, int n_in,
                              void* d_out, int out_size) {
    const float* regression     = (const float*)d_in[0];
    const float* classification = (const float*)d_in[1];
    const float* anchors        = (const float*)d_in[2];
    const float* gt_BB          = (const float*)d_in[3];
    float* out = (float*)d_out;

    dim3 grid(XBLK, B_N);
    fl_main_kernel<<<grid, TPB>>>(regression, classification, anchors, gt_BB, out);
}

// round 12
// speedup vs baseline: 1.0171x; 1.0007x over previous
#include <cuda_runtime.h>
#include <cuda_bf16.h>

#define A_N   49104
#define B_N   8
#define C_N   80
#define M_N   64
#define TPB   256
#define XBLK  ((A_N + TPB - 1) / TPB)   /* 192 */
#define NBLK  (XBLK * B_N)              /* 1536 */
#define NWARP (TPB/32)

// Per-block partials (fully overwritten each launch before being read)
__device__ float    p_cls[NBLK];
__device__ float    p_reg[NBLK];
__device__ int      p_np[NBLK];
__device__ unsigned g_done = 0;         // reset by last block each launch

__device__ __forceinline__ float rcp_fast(float x) {
    float y; asm("rcp.approx.f32 %0, %1;" : "=f"(y) : "f"(x)); return y;
}
__device__ __forceinline__ float smooth_l1(float d) {
    return (d <= (1.0f/9.0f)) ? 4.5f * d * d : d - (0.5f/9.0f);
}
// Hot focal quad: sum of p^2*log2(1-p), FFMA-chained (inputs in (1e-3,1-1e-3))
__device__ __forceinline__ float bt4s(float4 v) {
    float l0 = __log2f(1.0f - v.x);
    float l1 = __log2f(1.0f - v.y);
    float l2 = __log2f(1.0f - v.z);
    float l3 = __log2f(1.0f - v.w);
    float t  = (v.x * v.x) * l0;
    t = fmaf(v.y * v.y, l1, t);
    t = fmaf(v.z * v.z, l2, t);
    t = fmaf(v.w * v.w, l3, t);
    return t;
}
__device__ __forceinline__ float bt(float p) {
    return p * p * __log2f(1.0f - p);
}
// Positive-class term, alpha folded: 0.25 * (1-p)^2 * log2(p)
__device__ __forceinline__ float pt(float p) {
    float q = 1.0f - p;
    return 0.25f * q * q * __log2f(p);
}

__global__ __launch_bounds__(TPB) void fl_main_kernel(
    const float* __restrict__ reg,    // [B, A, 4]
    const float* __restrict__ cls,    // [B, A, C]
    const float* __restrict__ anc,    // [1, A, 4]
    const float* __restrict__ gt,     // [B, M, 5]
    float* __restrict__ out)          // [2]
{
    __shared__ float4 s_gbox[M_N];
    __shared__ float  s_garea[M_N];
    __shared__ int    s_gcls[M_N];
    __shared__ float  s_flag[TPB];    // 0 = ignore/inactive, 0.75 = active
    __shared__ float  s_rc[NWARP];
    __shared__ float  s_rr[NWARP];
    __shared__ int    s_rn[NWARP];
    __shared__ float  s_bl[2 * B_N];
    __shared__ bool   s_last;

    const int b    = blockIdx.y;
    const int tid  = threadIdx.x;
    const int lane = tid & 31;

    if (tid < M_N) {
        const float* g = gt + ((size_t)b * M_N + tid) * 5;
        float x1 = g[0], y1 = g[1], x2 = g[2], y2 = g[3], c = g[4];
        if (c < 0.0f) { x1 = y1 = x2 = y2 = 0.0f; }  // invalid gt never wins argmax
        s_gbox[tid]  = make_float4(x1, y1, x2, y2);
        s_garea[tid] = (x2 - x1) * (y2 - y1);
        s_gcls[tid]  = (int)c;
    }
    __syncthreads();

    const int a       = blockIdx.x * TPB + tid;
    const float* clsb = cls + (size_t)b * A_N * C_N;

    float flag = 0.0f;   // 0 or 0.75
    float accS = 0.0f;   // pos-class correction (fully weighted, log2 units)
    float accR = 0.0f;   // smooth-L1 sum
    int   npos = 0;

    // ================= Phase 1: IoU argmax + assignment ====================
    if (a < A_N) {
        const float4 ab = *reinterpret_cast<const float4*>(anc + (size_t)a * 4);
        const float aw  = fabsf(ab.x - ab.z);
        const float ah  = fabsf(ab.y - ab.w);
        const float acx = ab.x + 0.5f * aw;
        const float acy = ab.y + 0.5f * ah;
        const float a_area = (ab.z - ab.x) * (ab.w - ab.y);

        // Packed-key argmax, SIGNED int max:
        //   u = iw+|iw| >= 0 ;  r = u*ih*rcp(S)  (<=0 whenever no overlap)
        //   key = bits(r)|m ; negative r -> negative int -> loses to any r>=0.
        int key0 = (int)0x80000000, key1 = (int)0x80000000;
        #pragma unroll 8
        for (int m = 0; m < M_N; m += 2) {
            {
                const float4 gb = s_gbox[m];
                float iw = fminf(ab.z, gb.z) - fmaxf(ab.x, gb.x);
                float ih = fminf(ab.w, gb.w) - fmaxf(ab.y, gb.y);
                float u  = iw + fabsf(iw);
                float r  = (u * ih) * rcp_fast(a_area + s_garea[m]);
                int kk = (int)((__float_as_uint(r) & 0xffffffc0u) | (unsigned)m);
                key0 = (kk > key0) ? kk : key0;
            }
            {
                const float4 gb = s_gbox[m + 1];
                float iw = fminf(ab.z, gb.z) - fmaxf(ab.x, gb.x);
                float ih = fminf(ab.w, gb.w) - fmaxf(ab.y, gb.y);
                float u  = iw + fabsf(iw);
                float r  = (u * ih) * rcp_fast(a_area + s_garea[m + 1]);
                int kk = (int)((__float_as_uint(r) & 0xffffffc0u) | (unsigned)(m + 1));
                key1 = (kk > key1) ? kk : key1;
            }
        }
        const int kmax = (key0 > key1) ? key0 : key1;
        const int bidx = kmax & 63;

        // Exact IoU of the winner for thresholding
        const float4 gb = s_gbox[bidx];
        float iw = fmaxf(fminf(ab.z, gb.z) - fmaxf(ab.x, gb.x), 0.0f);
        float ih = fmaxf(fminf(ab.w, gb.w) - fmaxf(ab.y, gb.y), 0.0f);
        float inter = iw * ih;
        float un    = (a_area + s_garea[bidx]) - inter;
        float iou   = __fdividef(inter, un);
        const bool pos = (iou >= 0.5f);
        const bool neg = (iou < 0.4f);
        if (pos | neg) flag = 0.75f;

        if (pos) {
            float gw0 = gb.z - gb.x, gh0 = gb.w - gb.y;
            float gcx = gb.x + 0.5f * gw0, gcy = gb.y + 0.5f * gh0;
            float gw = fmaxf(gw0, 1.0f), gh = fmaxf(gh0, 1.0f);
            float tdx = __fdividef(gcx - acx, aw);
            float tdy = __fdividef(gcy - acy, ah);
            float tdh = __logf(__fdividef(gh, ah));
            float tdw = __logf(__fdividef(gw, aw));
            const float4 rg = *reinterpret_cast<const float4*>(reg + ((size_t)b * A_N + a) * 4);
            accR = smooth_l1(fabsf(tdx - rg.x)) + smooth_l1(fabsf(tdy - rg.y))
                 + smooth_l1(fabsf(tdh - rg.z)) + smooth_l1(fabsf(tdw - rg.w));
            npos = 1;
            // replace 0.75*base with the alpha-weighted positive term at (a,cid)
            const int cid = s_gcls[bidx];
            const float p = clsb[(size_t)a * C_N + cid];
            accS = pt(p) - 0.75f * bt(p);
        }
    }
    s_flag[tid] = flag;
    __syncwarp();

    // ====== Phase 2: flag-weighted focal stream (coalesced, branchless) ====
    const int sbase = tid & ~31;
    const int wbase = blockIdx.x * TPB + sbase;
    float accB0 = 0.0f, accB1 = 0.0f;

    if (wbase + 32 <= A_N) {
        // per-lane base pointer -> loads become immediate-offset LDGs
        const float4* tp = reinterpret_cast<const float4*>(
            clsb + (size_t)wbase * C_N) + lane;
        // flag index (lane+32k)/20 has period 5 in k: al(k)=alb[k%5]+8*(k/5)
        int alb[5];
        #pragma unroll
        for (int i = 0; i < 5; i++)
            alb[i] = (int)(((unsigned)lane + 32u * (unsigned)i) / 20u);

        #pragma unroll
        for (int k = 0; k < 20; k += 2) {
            const float fl0 = s_flag[sbase + alb[k % 5]       + 8 * (k / 5)];
            const float fl1 = s_flag[sbase + alb[(k + 1) % 5] + 8 * ((k + 1) / 5)];
            const float4 v0 = tp[32 * k];
            const float4 v1 = tp[32 * (k + 1)];
            accB0 = fmaf(fl0, bt4s(v0), accB0);
            accB1 = fmaf(fl1, bt4s(v1), accB1);
        }
    } else {
        // Tail (last x-block only): guarded
        const float4* wp = reinterpret_cast<const float4*>(clsb + (size_t)wbase * C_N);
        for (int k = 0; k < 20; k++) {
            const int f  = lane + 32 * k;
            const int al = f / 20;
            if (wbase + al < A_N) {
                const float fl = s_flag[sbase + al];
                accB0 = fmaf(fl, bt4s(wp[f]), accB0);
            }
        }
    }

    float accC = (accB0 + accB1) + accS;

    // ================= Block reduction -> per-block partials ===============
    #pragma unroll
    for (int o = 16; o > 0; o >>= 1) {
        accC += __shfl_down_sync(0xffffffffu, accC, o);
        accR += __shfl_down_sync(0xffffffffu, accR, o);
        npos += __shfl_down_sync(0xffffffffu, npos, o);
    }
    if (lane == 0) { s_rc[tid >> 5] = accC; s_rr[tid >> 5] = accR; s_rn[tid >> 5] = npos; }
    __syncthreads();

    const int blk = b * XBLK + blockIdx.x;
    if (tid == 0) {
        float c = 0.0f, r = 0.0f; int n = 0;
        #pragma unroll
        for (int w = 0; w < NWARP; w++) { c += s_rc[w]; r += s_rr[w]; n += s_rn[w]; }
        p_cls[blk] = c; p_reg[blk] = r; p_np[blk] = n;
        __threadfence();
        unsigned done = atomicAdd(&g_done, 1u);
        s_last = (done == NBLK - 1);
    }
    __syncthreads();

    // ================= Last block finalizes ================================
    if (s_last) {
        __threadfence();
        const int w = tid >> 5;
        if (w < B_N) {
            float c = 0.0f, r = 0.0f, n = 0.0f;
            for (int i = lane; i < XBLK; i += 32) {
                const int idx = w * XBLK + i;
                c += p_cls[idx]; r += p_reg[idx]; n += (float)p_np[idx];
            }
            #pragma unroll
            for (int o = 16; o > 0; o >>= 1) {
                c += __shfl_down_sync(0xffffffffu, c, o);
                r += __shfl_down_sync(0xffffffffu, r, o);
                n += __shfl_down_sync(0xffffffffu, n, o);
            }
            if (lane == 0) {
                const float NEG_LN2 = -0.69314718055994530942f;
                s_bl[w]       = NEG_LN2 * c / fmaxf(n, 1.0f);
                s_bl[B_N + w] = (n > 0.0f) ? r / (4.0f * n) : 0.0f;
            }
        }
        __syncthreads();
        if (tid == 0) {
            float cs = 0.0f, rs = 0.0f;
            #pragma unroll
            for (int i = 0; i < B_N; i++) { cs += s_bl[i]; rs += s_bl[B_N + i]; }
            out[0] = cs * (1.0f / (float)B_N);
            out[1] = rs * (1.0f / (float)B_N) * 50.0f;
            atomicExch(&g_done, 0u);   // reset for next graph replay
        }
    }
}

extern "C" void kernel_launch(void* const* d_in, const int* in_sizes, int n_in,
                              void* d_out, int out_size) {
    const float* regression     = (const float*)d_in[0];
    const float* classification = (const float*)d_in[1];
    const float* anchors        = (const float*)d_in[2];
    const float* gt_BB          = (const float*)d_in[3];
    float* out = (float*)d_out;

    dim3 grid(XBLK, B_N);
    fl_main_kernel<<<grid, TPB>>>(regression, classification, anchors, gt_BB, out);
}

// round 13
// speedup vs baseline: 1.0539x; 1.0362x over previous
#include <cuda_runtime.h>
#include <cuda_bf16.h>

#define A_N   49104
#define B_N   8
#define C_N   80
#define M_N   64
#define TPB   256
#define XBLK  ((A_N + TPB - 1) / TPB)   /* 192 */
#define NBLK  (XBLK * B_N)              /* 1536 */
#define NWARP (TPB/32)

typedef unsigned long long u64t;

// Per-block partials (fully overwritten each launch before being read)
__device__ float    p_cls[NBLK];
__device__ float    p_reg[NBLK];
__device__ int      p_np[NBLK];
__device__ unsigned g_done = 0;         // reset by last block each launch

// ---------------- packed f32x2 helpers (Blackwell) ----------------
__device__ __forceinline__ u64t pk2(float a, float b) {
    u64t r; asm("mov.b64 %0, {%1, %2};" : "=l"(r) : "f"(a), "f"(b)); return r;
}
__device__ __forceinline__ void upk2(u64t v, float& a, float& b) {
    asm("mov.b64 {%0, %1}, %2;" : "=f"(a), "=f"(b) : "l"(v));
}
__device__ __forceinline__ u64t fma2(u64t a, u64t b, u64t c) {
    u64t d; asm("fma.rn.f32x2 %0, %1, %2, %3;" : "=l"(d) : "l"(a), "l"(b), "l"(c)); return d;
}
__device__ __forceinline__ u64t mul2(u64t a, u64t b) {
    u64t d; asm("mul.rn.f32x2 %0, %1, %2;" : "=l"(d) : "l"(a), "l"(b)); return d;
}
#define NEG1P 0xbf800000bf800000ull   /* (-1.f, -1.f) */
#define ONE1P 0x3f8000003f800000ull   /* ( 1.f,  1.f) */

__device__ __forceinline__ float rcp_fast(float x) {
    float y; asm("rcp.approx.f32 %0, %1;" : "=f"(y) : "f"(x)); return y;
}
__device__ __forceinline__ float smooth_l1(float d) {
    return (d <= (1.0f/9.0f)) ? 4.5f * d * d : d - (0.5f/9.0f);
}
__device__ __forceinline__ float bt(float p) {           // p^2*log2(1-p)
    return p * p * __log2f(1.0f - p);
}
__device__ __forceinline__ float pt(float p) {           // 0.25*(1-p)^2*log2(p)
    float q = 1.0f - p;
    return 0.25f * q * q * __log2f(p);
}
// Packed hot quad: sum of p^2*log2(1-p) over 4 elems (2 packed FMA + 2 packed MUL)
__device__ __forceinline__ float bt4p(float4 v) {
    u64t v01 = pk2(v.x, v.y);
    u64t v23 = pk2(v.z, v.w);
    u64t q01 = fma2(v01, NEG1P, ONE1P);   // (1-p0, 1-p1)
    u64t q23 = fma2(v23, NEG1P, ONE1P);
    u64t s01 = mul2(v01, v01);            // (p0^2, p1^2)
    u64t s23 = mul2(v23, v23);
    float qa, qb, qc, qd, sa, sb, sc, sd;
    upk2(q01, qa, qb); upk2(q23, qc, qd);
    upk2(s01, sa, sb); upk2(s23, sc, sd);
    float l0 = __log2f(qa), l1 = __log2f(qb), l2 = __log2f(qc), l3 = __log2f(qd);
    float t  = sa * l0;
    t = fmaf(sb, l1, t);
    t = fmaf(sc, l2, t);
    t = fmaf(sd, l3, t);
    return t;
}

__global__ __launch_bounds__(TPB) void fl_main_kernel(
    const float* __restrict__ reg,    // [B, A, 4]
    const float* __restrict__ cls,    // [B, A, C]
    const float* __restrict__ anc,    // [1, A, 4]
    const float* __restrict__ gt,     // [B, M, 5]
    float* __restrict__ out)          // [2]
{
    __shared__ float4 s_gbox[M_N];
    __shared__ float  s_garea[M_N];
    __shared__ int    s_gcls[M_N];
    __shared__ float  s_flag[TPB];    // 0 = ignore/inactive, 0.75 = active
    __shared__ float  s_rc[NWARP];
    __shared__ float  s_rr[NWARP];
    __shared__ int    s_rn[NWARP];
    __shared__ float  s_bl[2 * B_N];
    __shared__ bool   s_last;

    const int b    = blockIdx.y;
    const int tid  = threadIdx.x;
    const int lane = tid & 31;

    if (tid < M_N) {
        const float* g = gt + ((size_t)b * M_N + tid) * 5;
        float x1 = g[0], y1 = g[1], x2 = g[2], y2 = g[3], c = g[4];
        if (c < 0.0f) { x1 = y1 = x2 = y2 = 0.0f; }  // invalid gt never wins argmax
        s_gbox[tid]  = make_float4(x1, y1, x2, y2);
        s_garea[tid] = (x2 - x1) * (y2 - y1);
        s_gcls[tid]  = (int)c;
    }
    __syncthreads();

    const int a       = blockIdx.x * TPB + tid;
    const float* clsb = cls + (size_t)b * A_N * C_N;

    float flag = 0.0f;   // 0 or 0.75
    float accS = 0.0f;   // pos-class correction (fully weighted, log2 units)
    float accR = 0.0f;   // smooth-L1 sum
    int   npos = 0;

    // ================= Phase 1: IoU argmax + assignment ====================
    if (a < A_N) {
        const float4 ab = *reinterpret_cast<const float4*>(anc + (size_t)a * 4);
        const float aw  = fabsf(ab.x - ab.z);
        const float ah  = fabsf(ab.y - ab.w);
        const float acx = ab.x + 0.5f * aw;
        const float acy = ab.y + 0.5f * ah;
        const float a_area = (ab.z - ab.x) * (ab.w - ab.y);

        // Packed-key argmax, SIGNED int max:
        //   (iw,ih) via one packed FMA; u = max(iw,0); r = u*ih*rcp(S) (<=0 if no overlap)
        //   key = (bits(r)&~63)|m ; negative r -> negative key -> loses to any r>=0.
        int key0 = (int)0x80000000, key1 = (int)0x80000000;
        #pragma unroll 8
        for (int m = 0; m < M_N; m += 2) {
            {
                const float4 gb = s_gbox[m];
                u64t mn = pk2(fminf(ab.z, gb.z), fminf(ab.w, gb.w));
                u64t mx = pk2(fmaxf(ab.x, gb.x), fmaxf(ab.y, gb.y));
                u64t d  = fma2(mx, NEG1P, mn);       // (iw, ih)
                float iw, ih; upk2(d, iw, ih);
                float u  = fmaxf(iw, 0.0f);
                float r  = (u * ih) * rcp_fast(a_area + s_garea[m]);
                int kk = (int)((__float_as_uint(r) & 0xffffffc0u) | (unsigned)m);
                key0 = (kk > key0) ? kk : key0;
            }
            {
                const float4 gb = s_gbox[m + 1];
                u64t mn = pk2(fminf(ab.z, gb.z), fminf(ab.w, gb.w));
                u64t mx = pk2(fmaxf(ab.x, gb.x), fmaxf(ab.y, gb.y));
                u64t d  = fma2(mx, NEG1P, mn);
                float iw, ih; upk2(d, iw, ih);
                float u  = fmaxf(iw, 0.0f);
                float r  = (u * ih) * rcp_fast(a_area + s_garea[m + 1]);
                int kk = (int)((__float_as_uint(r) & 0xffffffc0u) | (unsigned)(m + 1));
                key1 = (kk > key1) ? kk : key1;
            }
        }
        const int kmax = (key0 > key1) ? key0 : key1;
        const int bidx = kmax & 63;

        // Exact IoU of the winner for thresholding
        const float4 gb = s_gbox[bidx];
        float iw = fmaxf(fminf(ab.z, gb.z) - fmaxf(ab.x, gb.x), 0.0f);
        float ih = fmaxf(fminf(ab.w, gb.w) - fmaxf(ab.y, gb.y), 0.0f);
        float inter = iw * ih;
        float un    = (a_area + s_garea[bidx]) - inter;
        float iou   = __fdividef(inter, un);
        const bool pos = (iou >= 0.5f);
        const bool neg = (iou < 0.4f);
        if (pos | neg) flag = 0.75f;

        if (pos) {
            float gw0 = gb.z - gb.x, gh0 = gb.w - gb.y;
            float gcx = gb.x + 0.5f * gw0, gcy = gb.y + 0.5f * gh0;
            float gw = fmaxf(gw0, 1.0f), gh = fmaxf(gh0, 1.0f);
            float tdx = __fdividef(gcx - acx, aw);
            float tdy = __fdividef(gcy - acy, ah);
            float tdh = __logf(__fdividef(gh, ah));
            float tdw = __logf(__fdividef(gw, aw));
            const float4 rg = *reinterpret_cast<const float4*>(reg + ((size_t)b * A_N + a) * 4);
            accR = smooth_l1(fabsf(tdx - rg.x)) + smooth_l1(fabsf(tdy - rg.y))
                 + smooth_l1(fabsf(tdh - rg.z)) + smooth_l1(fabsf(tdw - rg.w));
            npos = 1;
            // replace 0.75*base with the alpha-weighted positive term at (a,cid)
            const int cid = s_gcls[bidx];
            const float p = clsb[(size_t)a * C_N + cid];
            accS = pt(p) - 0.75f * bt(p);
        }
    }
    s_flag[tid] = flag;
    __syncwarp();

    // ====== Phase 2: flag-weighted focal stream (coalesced, branchless) ====
    const int sbase = tid & ~31;
    const int wbase = blockIdx.x * TPB + sbase;
    float accB0 = 0.0f, accB1 = 0.0f;

    if (wbase + 32 <= A_N) {
        // per-lane base pointer -> loads become immediate-offset LDGs
        const float4* tp = reinterpret_cast<const float4*>(
            clsb + (size_t)wbase * C_N) + lane;
        // flag index (lane+32k)/20 has period 5 in k: al(k)=alb[k%5]+8*(k/5)
        int alb[5];
        #pragma unroll
        for (int i = 0; i < 5; i++)
            alb[i] = (int)(((unsigned)lane + 32u * (unsigned)i) / 20u);

        #pragma unroll
        for (int k = 0; k < 20; k += 2) {
            const float fl0 = s_flag[sbase + alb[k % 5]       + 8 * (k / 5)];
            const float fl1 = s_flag[sbase + alb[(k + 1) % 5] + 8 * ((k + 1) / 5)];
            const float4 v0 = tp[32 * k];
            const float4 v1 = tp[32 * (k + 1)];
            accB0 = fmaf(fl0, bt4p(v0), accB0);
            accB1 = fmaf(fl1, bt4p(v1), accB1);
        }
    } else {
        // Tail (last x-block only): guarded
        const float4* wp = reinterpret_cast<const float4*>(clsb + (size_t)wbase * C_N);
        for (int k = 0; k < 20; k++) {
            const int f  = lane + 32 * k;
            const int al = f / 20;
            if (wbase + al < A_N) {
                const float fl = s_flag[sbase + al];
                accB0 = fmaf(fl, bt4p(wp[f]), accB0);
            }
        }
    }

    float accC = (accB0 + accB1) + accS;

    // ================= Block reduction -> per-block partials ===============
    #pragma unroll
    for (int o = 16; o > 0; o >>= 1) {
        accC += __shfl_down_sync(0xffffffffu, accC, o);
        accR += __shfl_down_sync(0xffffffffu, accR, o);
        npos += __shfl_down_sync(0xffffffffu, npos, o);
    }
    if (lane == 0) { s_rc[tid >> 5] = accC; s_rr[tid >> 5] = accR; s_rn[tid >> 5] = npos; }
    __syncthreads();

    const int blk = b * XBLK + blockIdx.x;
    if (tid == 0) {
        float c = 0.0f, r = 0.0f; int n = 0;
        #pragma unroll
        for (int w = 0; w < NWARP; w++) { c += s_rc[w]; r += s_rr[w]; n += s_rn[w]; }
        p_cls[blk] = c; p_reg[blk] = r; p_np[blk] = n;
        __threadfence();
        unsigned done = atomicAdd(&g_done, 1u);
        s_last = (done == NBLK - 1);
    }
    __syncthreads();

    // ================= Last block finalizes ================================
    if (s_last) {
        __threadfence();
        const int w = tid >> 5;
        if (w < B_N) {
            float c = 0.0f, r = 0.0f, n = 0.0f;
            for (int i = lane; i < XBLK; i += 32) {
                const int idx = w * XBLK + i;
                c += p_cls[idx]; r += p_reg[idx]; n += (float)p_np[idx];
            }
            #pragma unroll
            for (int o = 16; o > 0; o >>= 1) {
                c += __shfl_down_sync(0xffffffffu, c, o);
                r += __shfl_down_sync(0xffffffffu, r, o);
                n += __shfl_down_sync(0xffffffffu, n, o);
            }
            if (lane == 0) {
                const float NEG_LN2 = -0.69314718055994530942f;
                s_bl[w]       = NEG_LN2 * c / fmaxf(n, 1.0f);
                s_bl[B_N + w] = (n > 0.0f) ? r / (4.0f * n) : 0.0f;
            }
        }
        __syncthreads();
        if (tid == 0) {
            float cs = 0.0f, rs = 0.0f;
            #pragma unroll
            for (int i = 0; i < B_N; i++) { cs += s_bl[i]; rs += s_bl[B_N + i]; }
            out[0] = cs * (1.0f / (float)B_N);
            out[1] = rs * (1.0f / (float)B_N) * 50.0f;
            atomicExch(&g_done, 0u);   // reset for next graph replay
        }
    }
}

extern "C" void kernel_launch(void* const* d_in, const int* in_sizes, int n_in,
                              void* d_out, int out_size) {
    const float* regression     = (const float*)d_in[0];
    const float* classification = (const float*)d_in[1];
    const float* anchors        = (const float*)d_in[2];
    const float* gt_BB          = (const float*)d_in[3];
    float* out = (float*)d_out;

    dim3 grid(XBLK, B_N);
    fl_main_kernel<<<grid, TPB>>>(regression, classification, anchors, gt_BB, out);
}